// round 15
// baseline (speedup 1.0000x reference)
#include <cuda_runtime.h>
#include <cuda_fp16.h>
#include <math.h>
#include <stdint.h>

// Problem shape (fixed by setup_inputs)
#define MROWS 32768          // B*L
#define BDIM  8
#define LSEQ  4096
#define HD    1024
#define NL    4
#define NCHK  32             // HD / BK
#define NCHK2 64             // two tiles back-to-back
#define RPB   4              // rows per LN block

// GEMM tiling: CTA 128x128, 4 warps (2x2), warp tile 64x64, BK=32
#define BM 128
#define BN 128
#define BK 32
#define NSTAGE 3
#define ROWB 80                           // (32+8) fp16 = 80 bytes per row
#define A_STG (BM * ROWB)                 // 10240
#define B_STG (BN * ROWB)                 // 10240
#define STG   (A_STG + B_STG)             // 20480
#define GEMM_SMEM (NSTAGE * STG)          // 61440 (x3 CTAs = 184KB <= 228KB)

// ---------------------------------------------------------------------------
// Scratch (device globals: allocation-free)
// ---------------------------------------------------------------------------
__device__ float g_bufA[(size_t)MROWS * HD];     // low half reused as fp16 Y1
__device__ float g_bufB[(size_t)MROWS * HD];     // fp16 F / fp16 Y2
__device__ __align__(256) __half g_A2[(size_t)MROWS * HD];    // fp16 A
__device__ __align__(256) __half g_Wt1[(size_t)HD * HD];      // lt_w^T fp16
__device__ __align__(256) __half g_Wt2[(size_t)HD * HD];      // ft_w^T fp16

// ---------------------------------------------------------------------------
// PTX helpers (sm_80-class features only: cp.async, ldmatrix, mma.sync)
// ---------------------------------------------------------------------------
__device__ __forceinline__ uint32_t smem_to_u32(const void* p) {
    uint32_t a;
    asm("{ .reg .u64 t; cvta.to.shared.u64 t, %1; cvt.u32.u64 %0, t; }" : "=r"(a) : "l"(p));
    return a;
}
__device__ __forceinline__ void cp_async16(uint32_t dst, const void* src) {
    asm volatile("cp.async.cg.shared.global [%0], [%1], 16;\n" :: "r"(dst), "l"(src) : "memory");
}
#define CP_COMMIT() asm volatile("cp.async.commit_group;" ::: "memory")
#define CP_WAIT1()  asm volatile("cp.async.wait_group 1;" ::: "memory")

__device__ __forceinline__ void ldsm_x4(uint32_t (&r)[4], uint32_t addr) {
    asm volatile("ldmatrix.sync.aligned.m8n8.x4.shared.b16 {%0,%1,%2,%3}, [%4];"
        : "=r"(r[0]), "=r"(r[1]), "=r"(r[2]), "=r"(r[3]) : "r"(addr));
}
__device__ __forceinline__ void mma16816(float (&c)[4],
                                         const uint32_t (&a)[4],
                                         uint32_t b0, uint32_t b1) {
    asm volatile(
        "mma.sync.aligned.m16n8k16.row.col.f32.f16.f16.f32 "
        "{%0,%1,%2,%3}, {%4,%5,%6,%7}, {%8,%9}, {%0,%1,%2,%3};"
        : "+f"(c[0]), "+f"(c[1]), "+f"(c[2]), "+f"(c[3])
        : "r"(a[0]), "r"(a[1]), "r"(a[2]), "r"(a[3]), "r"(b0), "r"(b1));
}

__device__ __forceinline__ float warp_sum(float v) {
    #pragma unroll
    for (int o = 16; o > 0; o >>= 1) v += __shfl_xor_sync(0xffffffffu, v, o);
    return v;
}

// N simultaneous block-wide sums with ONE store+barrier round (256 thr, 8 warps)
template <int N>
__device__ __forceinline__ void blk_reduceN(float (&v)[N], float* sbuf)
{
    #pragma unroll
    for (int k = 0; k < N; ++k) v[k] = warp_sum(v[k]);
    const int lane = threadIdx.x & 31, w = threadIdx.x >> 5;
    if (lane == 0) {
        #pragma unroll
        for (int k = 0; k < N; ++k) sbuf[k * 8 + w] = v[k];
    }
    __syncthreads();
    if (threadIdx.x < 8 * N) {
        float x = sbuf[threadIdx.x];
        x += __shfl_xor_sync(0xffffffffu, x, 4);
        x += __shfl_xor_sync(0xffffffffu, x, 2);
        x += __shfl_xor_sync(0xffffffffu, x, 1);
        if ((threadIdx.x & 7) == 0) sbuf[8 * N + (threadIdx.x >> 3)] = x;
    }
    __syncthreads();
    #pragma unroll
    for (int k = 0; k < N; ++k) v[k] = sbuf[8 * N + k];
}

// ---------------------------------------------------------------------------
// fp32 -> fp16 conversion of A [M, HD]
// ---------------------------------------------------------------------------
__global__ __launch_bounds__(256) void convA_kernel(
    const float* __restrict__ A, __half* __restrict__ A2)
{
    const size_t i = (size_t)blockIdx.x * 256 + threadIdx.x;
    const float4 v = *(const float4*)(A + i * 4);
    __half h[4];
    h[0] = __float2half_rn(v.x); h[1] = __float2half_rn(v.y);
    h[2] = __float2half_rn(v.z); h[3] = __float2half_rn(v.w);
    ((unsigned long long*)A2)[i] = *(const unsigned long long*)h;
}

// Both weights in one launch: W1,W2 [HD,HD] fp32 -> Wt1,Wt2 [n][k] fp16
__global__ __launch_bounds__(256) void convW2_kernel(
    const float* __restrict__ W1, __half* __restrict__ Wt1,
    const float* __restrict__ W2, __half* __restrict__ Wt2)
{
    const int which = blockIdx.x >= (HD * HD) / 256;
    const int idx = (blockIdx.x - which * ((HD * HD) / 256)) * 256 + threadIdx.x;
    const int n = idx & (HD - 1);
    const int k = idx >> 10;
    const float* W = which ? W2 : W1;
    __half* Wt = which ? Wt2 : Wt1;
    Wt[(size_t)n * HD + k] = __float2half_rn(W[(size_t)k * HD + n]);
}

// ---------------------------------------------------------------------------
// mma.sync GEMM (UNCHANGED): 2 M-tiles per CTA, seamless 64-chunk pipeline,
// CTA 128x128, 4 warps, 64x64 warp tiles, 3 stages, 3 CTAs/SM.
// ---------------------------------------------------------------------------
template <typename OutT>
__global__ __launch_bounds__(128, 3) void gemm_mma_kernel(
    const __half* __restrict__ A2,
    const __half* __restrict__ Wt,
    const float* __restrict__ bias,
    OutT* __restrict__ C)
{
    extern __shared__ char smem_raw[];
    const uint32_t sbase = smem_to_u32(smem_raw);

    const int tid = threadIdx.x;
    const int wid = tid >> 5;
    const int lane = tid & 31;
    const int m_base = blockIdx.y * (2 * BM);
    const int n0 = blockIdx.x * BN;

    const int wm = (wid >> 1) * 64;
    const int wn = (wid & 1) * 64;

    const int lr = tid >> 2;
    const int lc = tid & 3;
    const __half* gB[4];
    #pragma unroll
    for (int j = 0; j < 4; ++j)
        gB[j] = Wt + (size_t)(n0 + lr + 32 * j) * HD + lc * 8;
    const __half* gA_t0 = A2 + (size_t)(m_base + lr) * HD + lc * 8;
    const __half* gA_t1 = gA_t0 + (size_t)BM * HD;

    const uint32_t sA_off = lr * ROWB + lc * 16;
    const uint32_t sB_off = A_STG + lr * ROWB + lc * 16;
    const uint32_t RSTEP32 = 32 * ROWB;
    const size_t   ARSTEP = (size_t)32 * HD;

    const int lrow = lane & 15;
    const int lkof = (lane >> 4) * 16;
    const uint32_t aAddrBase = sbase + (wm + lrow) * ROWB + lkof;
    const uint32_t bAddrBase = sbase + A_STG + (wn + lrow) * ROWB + lkof;

    const int g = lane >> 2;
    const int t = lane & 3;

    float acc[4][8][4];
    #pragma unroll
    for (int i = 0; i < 4; ++i)
        #pragma unroll
        for (int j = 0; j < 8; ++j)
            #pragma unroll
            for (int q = 0; q < 4; ++q) acc[i][j][q] = 0.0f;

    auto issue = [&](int q, int stage) {
        const uint32_t sb = sbase + stage * STG;
        const size_t go = (size_t)(q & 31) * BK;
        const __half* gA = (q < NCHK) ? gA_t0 : gA_t1;
        #pragma unroll
        for (int j = 0; j < 4; ++j) {
            cp_async16(sb + sA_off + j * RSTEP32, gA + j * ARSTEP + go);
            cp_async16(sb + sB_off + j * RSTEP32, gB[j] + go);
        }
    };

    issue(0, 0); CP_COMMIT();
    issue(1, 1); CP_COMMIT();

    int s_c = 0;
    int s_q = 2;
    #pragma unroll 1
    for (int kc = 0; kc < NCHK2; ++kc) {
        CP_WAIT1();
        __syncthreads();

        const int q = kc + 2;
        if (q < NCHK2) issue(q, s_q);
        CP_COMMIT();

        const uint32_t stg = s_c * STG;
        #pragma unroll
        for (int ks = 0; ks < 2; ++ks) {
            uint32_t a[4][4], b[4][4];
            const uint32_t kb = stg + ks * 32;
            #pragma unroll
            for (int i = 0; i < 4; ++i)
                ldsm_x4(a[i], aAddrBase + kb + i * (16 * ROWB));
            #pragma unroll
            for (int j = 0; j < 4; ++j)
                ldsm_x4(b[j], bAddrBase + kb + j * (16 * ROWB));
            #pragma unroll
            for (int i = 0; i < 4; ++i) {
                #pragma unroll
                for (int j = 0; j < 4; ++j) {
                    mma16816(acc[i][2 * j + 0], a[i], b[j][0], b[j][2]);
                    mma16816(acc[i][2 * j + 1], a[i], b[j][1], b[j][3]);
                }
            }
        }

        if ((kc & (NCHK - 1)) == NCHK - 1) {
            const int m0 = m_base + (kc >> 5) * BM;
            #pragma unroll
            for (int i = 0; i < 4; ++i) {
                const int row = m0 + wm + i * 16 + g;
                #pragma unroll
                for (int j = 0; j < 8; ++j) {
                    const int col = n0 + wn + j * 8 + t * 2;
                    const float b0 = bias[col], b1 = bias[col + 1];
                    const float v00 = acc[i][j][0] + b0, v01 = acc[i][j][1] + b1;
                    const float v10 = acc[i][j][2] + b0, v11 = acc[i][j][3] + b1;
                    if (sizeof(OutT) == 4) {
                        *(float2*)((float*)C + (size_t)row * HD + col) = make_float2(v00, v01);
                        *(float2*)((float*)C + (size_t)(row + 8) * HD + col) = make_float2(v10, v11);
                    } else {
                        *(__half2*)((__half*)C + (size_t)row * HD + col) = __floats2half2_rn(v00, v01);
                        *(__half2*)((__half*)C + (size_t)(row + 8) * HD + col) = __floats2half2_rn(v10, v11);
                    }
                    acc[i][j][0] = 0.f; acc[i][j][1] = 0.f;
                    acc[i][j][2] = 0.f; acc[i][j][3] = 0.f;
                }
            }
        }

        if (++s_c == NSTAGE) s_c = 0;
        if (++s_q == NSTAGE) s_q = 0;
    }
}

// ---------------------------------------------------------------------------
// LN1 + hierarchical fusion: 4 rows per block, SINGLE batched reduction.
// Scores via LN-hoisted identity:
//   dot(t, e_n) = rstd*(dot(y*g, e_n) - mu*dot(g, e_n)) + dot(b, e_n)
// v32 layout: [0..3] sum_r, [4..7] sumsq_r, [8..23] dot(y_r*g, e_n),
//             [24..27] dot(g, e_n), [28..31] dot(b, e_n)
// ---------------------------------------------------------------------------
__global__ __launch_bounds__(256) void ln1_fusion_kernel(
    const __half* __restrict__ Y, const float* __restrict__ masks,
    const float* __restrict__ emb,
    const float* __restrict__ g, const float* __restrict__ bvec,
    __half* __restrict__ Fout)
{
    __shared__ float sbuf[288];

    const int row0 = blockIdx.x * RPB;
    const int c = threadIdx.x * 4;

    const float4 gv = __ldg((const float4*)(g + c));
    const float4 bv = __ldg((const float4*)(bvec + c));
    const float4 e0 = __ldg((const float4*)(emb + 0 * HD + c));
    const float4 e1 = __ldg((const float4*)(emb + 1 * HD + c));
    const float4 e2 = __ldg((const float4*)(emb + 2 * HD + c));
    const float4 e3 = __ldg((const float4*)(emb + 3 * HD + c));

    float y[RPB][4];
    float v32[32];

    #pragma unroll
    for (int r = 0; r < RPB; ++r) {
        const uint2 yraw = *(const uint2*)(Y + (size_t)(row0 + r) * HD + c);
        const float2 ya = __half22float2(*(const __half2*)&yraw.x);
        const float2 yb = __half22float2(*(const __half2*)&yraw.y);
        y[r][0] = ya.x; y[r][1] = ya.y; y[r][2] = yb.x; y[r][3] = yb.y;
        v32[r]       = ya.x + ya.y + yb.x + yb.y;
        v32[RPB + r] = ya.x * ya.x + ya.y * ya.y + yb.x * yb.x + yb.y * yb.y;
        const float yg0 = ya.x * gv.x, yg1 = ya.y * gv.y;
        const float yg2 = yb.x * gv.z, yg3 = yb.y * gv.w;
        v32[8 + r * 4 + 0] = yg0 * e0.x + yg1 * e0.y + yg2 * e0.z + yg3 * e0.w;
        v32[8 + r * 4 + 1] = yg0 * e1.x + yg1 * e1.y + yg2 * e1.z + yg3 * e1.w;
        v32[8 + r * 4 + 2] = yg0 * e2.x + yg1 * e2.y + yg2 * e2.z + yg3 * e2.w;
        v32[8 + r * 4 + 3] = yg0 * e3.x + yg1 * e3.y + yg2 * e3.z + yg3 * e3.w;
    }
    // row-independent constants: dot(g, e_n), dot(b, e_n)
    v32[24] = gv.x * e0.x + gv.y * e0.y + gv.z * e0.z + gv.w * e0.w;
    v32[25] = gv.x * e1.x + gv.y * e1.y + gv.z * e1.z + gv.w * e1.w;
    v32[26] = gv.x * e2.x + gv.y * e2.y + gv.z * e2.z + gv.w * e2.w;
    v32[27] = gv.x * e3.x + gv.y * e3.y + gv.z * e3.z + gv.w * e3.w;
    v32[28] = bv.x * e0.x + bv.y * e0.y + bv.z * e0.z + bv.w * e0.w;
    v32[29] = bv.x * e1.x + bv.y * e1.y + bv.z * e1.z + bv.w * e1.w;
    v32[30] = bv.x * e2.x + bv.y * e2.y + bv.z * e2.z + bv.w * e2.w;
    v32[31] = bv.x * e3.x + bv.y * e3.y + bv.z * e3.z + bv.w * e3.w;

    blk_reduceN<32>(v32, sbuf);

    #pragma unroll
    for (int r = 0; r < RPB; ++r) {
        const float mu   = v32[r] * (1.0f / HD);
        const float var  = v32[RPB + r] * (1.0f / HD) - mu * mu;
        const float rstd = rsqrtf(var + 1e-5f);

        const float sc0 = rstd * (v32[8 + r * 4 + 0] - mu * v32[24]) + v32[28];
        const float sc1 = rstd * (v32[8 + r * 4 + 1] - mu * v32[25]) + v32[29];
        const float sc2 = rstd * (v32[8 + r * 4 + 2] - mu * v32[26]) + v32[30];
        const float sc3 = rstd * (v32[8 + r * 4 + 3] - mu * v32[27]) + v32[31];

        const float4 mk = __ldg((const float4*)(masks + (size_t)(row0 + r) * 4));
        const float wn0 = (mk.x > 0.5f) ? expf(sc0) : 0.0f;
        const float wn1 = (mk.y > 0.5f) ? expf(sc1) : 0.0f;
        const float wn2 = (mk.z > 0.5f) ? expf(sc2) : 0.0f;
        const float wn3 = (mk.w > 0.5f) ? expf(sc3) : 0.0f;
        const float tot = wn0 + wn1 + wn2 + wn3;
        const float inv = (tot > 1e-8f) ? (1.0f / tot) : 1.0f;
        const float q0 = wn0 * inv, q1 = wn1 * inv, q2 = wn2 * inv, q3 = wn3 * inv;

        const float gsum = q0 * sc0 + q1 * sc1 + q2 * sc2 + q3 * sc3;
        const float gate = 1.0f / (1.0f + expf(-gsum * (1.0f / HD)));
        const float og = 1.0f - gate;

        const float t0 = (y[r][0] - mu) * rstd * gv.x + bv.x;
        const float t1 = (y[r][1] - mu) * rstd * gv.y + bv.y;
        const float t2 = (y[r][2] - mu) * rstd * gv.z + bv.z;
        const float t3 = (y[r][3] - mu) * rstd * gv.w + bv.w;

        const float f0 = q0 * e0.x + q1 * e1.x + q2 * e2.x + q3 * e3.x;
        const float f1 = q0 * e0.y + q1 * e1.y + q2 * e2.y + q3 * e3.y;
        const float f2 = q0 * e0.z + q1 * e1.z + q2 * e2.z + q3 * e3.z;
        const float f3 = q0 * e0.w + q1 * e1.w + q2 * e2.w + q3 * e3.w;

        const __half2 h01 = __floats2half2_rn(gate * f0 + og * t0, gate * f1 + og * t1);
        const __half2 h23 = __floats2half2_rn(gate * f2 + og * t2, gate * f3 + og * t3);
        __half2 hv[2] = {h01, h23};
        *(uint2*)(Fout + (size_t)(row0 + r) * HD + c) = *(uint2*)hv;
    }
}

// ---------------------------------------------------------------------------
// Multi-scale windowed means along L, __half2 vectorized (one thread per h-pair)
// ---------------------------------------------------------------------------
#define H2 512   // HD / 2

__global__ __launch_bounds__(256) void multiscale_kernel(
    const __half2* __restrict__ F2, __half2* __restrict__ O2)
{
    const int L = LSEQ;
    const int SL = 128;

    const int gtid = blockIdx.x * 256 + threadIdx.x;
    const int h = gtid & (H2 - 1);
    const int rest = gtid >> 9;
    const int b = rest & 7;
    const int strip = rest >> 3;
    const int s0 = strip * SL;

    const __half2* base = F2 + (size_t)b * L * H2 + h;
    __half2* oA = O2 + (size_t)b * L * H2 + h;

    const float SW3  = (float)(1.0 / (1.0 + 1.0986122886681098));
    const float SW7  = (float)(1.0 / (1.0 + 1.9459101090932196));
    const float SW15 = (float)(1.0 / (1.0 + 2.7080502011022101));

    if (strip > 0 && strip < 31) {
        float2 ring[16];
        #pragma unroll
        for (int j = -8; j <= 6; ++j)
            ring[j & 15] = __half22float2(base[(size_t)(s0 + j) * H2]);

        float2 s3 = {0.f, 0.f}, s7 = {0.f, 0.f}, s15 = {0.f, 0.f};
        #pragma unroll
        for (int j = -8; j <= 6; ++j) {
            const float2 v = ring[j & 15];
            const int d = j + 1;
            if (d >= -7 && d <= 7) { s15.x += v.x; s15.y += v.y; }
            if (d >= -3 && d <= 3) { s7.x  += v.x; s7.y  += v.y; }
            if (d >= -1 && d <= 1) { s3.x  += v.x; s3.y  += v.y; }
        }

        const float w3 = SW3 * (1.0f / 3.0f);
        const float w7 = SW7 * (1.0f / 7.0f);
        const float w15 = SW15 * (1.0f / 15.0f);

        #pragma unroll 1
        for (int cch = 0; cch < SL; cch += 16) {
            #pragma unroll
            for (int i = 0; i < 16; ++i) {
                const int l = s0 + cch + i;
                const float2 nv = __half22float2(base[(size_t)(l + 7) * H2]);
                ring[(i + 7) & 15] = nv;
                s3.x  += ring[(i + 1) & 15].x - ring[(i - 2) & 15].x;
                s3.y  += ring[(i + 1) & 15].y - ring[(i - 2) & 15].y;
                s7.x  += ring[(i + 3) & 15].x - ring[(i - 4) & 15].x;
                s7.y  += ring[(i + 3) & 15].y - ring[(i - 4) & 15].y;
                s15.x += nv.x               - ring[(i - 8) & 15].x;
                s15.y += nv.y               - ring[(i - 8) & 15].y;
                const float2 s1 = ring[i & 15];
                const float ox = s1.x + s3.x * w3 + s7.x * w7 + s15.x * w15;
                const float oy = s1.y + s3.y * w3 + s7.y * w7 + s15.y * w15;
                oA[(size_t)l * H2] = __floats2half2_rn(ox, oy);
            }
        }
    } else {
        for (int l = s0; l < s0 + SL; ++l) {
            float2 s3 = {0.f, 0.f}, s7 = {0.f, 0.f}, s15 = {0.f, 0.f};
            #pragma unroll
            for (int j = -7; j <= 7; ++j) {
                const int p = l + j;
                float2 v = {0.f, 0.f};
                if (p >= 0 && p < L) v = __half22float2(base[(size_t)p * H2]);
                s15.x += v.x; s15.y += v.y;
                if (j >= -3 && j <= 3) { s7.x += v.x; s7.y += v.y; }
                if (j >= -1 && j <= 1) { s3.x += v.x; s3.y += v.y; }
            }
            const float2 s1 = __half22float2(base[(size_t)l * H2]);
            const float c3  = 1.0f / (float)(min(l + 2, L) - max(l - 1, 0));
            const float c7  = 1.0f / (float)(min(l + 4, L) - max(l - 3, 0));
            const float c15 = 1.0f / (float)(min(l + 8, L) - max(l - 7, 0));
            const float ox = s1.x + SW3 * s3.x * c3 + SW7 * s7.x * c7 + SW15 * s15.x * c15;
            const float oy = s1.y + SW3 * s3.y * c3 + SW7 * s7.y * c7 + SW15 * s15.y * c15;
            oA[(size_t)l * H2] = __floats2half2_rn(ox, oy);
        }
    }
}

// ---------------------------------------------------------------------------
// LN2 + residual: 4 rows per block, batched dual reductions
// ---------------------------------------------------------------------------
__global__ __launch_bounds__(256) void ln2_res_kernel(
    const __half* __restrict__ Y, const float* __restrict__ X,
    const float* __restrict__ g, const float* __restrict__ bvec,
    float* __restrict__ out)
{
    __shared__ float sbuf[72];
    const int row0 = blockIdx.x * RPB;
    const int c = threadIdx.x * 4;

    const float4 gv = __ldg((const float4*)(g + c));
    const float4 bv = __ldg((const float4*)(bvec + c));

    float y[RPB][4];
    float v8[8];
    #pragma unroll
    for (int r = 0; r < RPB; ++r) {
        const uint2 yraw = *(const uint2*)(Y + (size_t)(row0 + r) * HD + c);
        const float2 ya = __half22float2(*(const __half2*)&yraw.x);
        const float2 yb = __half22float2(*(const __half2*)&yraw.y);
        y[r][0] = ya.x; y[r][1] = ya.y; y[r][2] = yb.x; y[r][3] = yb.y;
        v8[r]       = ya.x + ya.y + yb.x + yb.y;
        v8[RPB + r] = ya.x * ya.x + ya.y * ya.y + yb.x * yb.x + yb.y * yb.y;
    }
    blk_reduceN<8>(v8, sbuf);

    #pragma unroll
    for (int r = 0; r < RPB; ++r) {
        const float mu   = v8[r] * (1.0f / HD);
        const float var  = v8[RPB + r] * (1.0f / HD) - mu * mu;
        const float rstd = rsqrtf(var + 1e-5f);
        const float4 xv = *(const float4*)(X + (size_t)(row0 + r) * HD + c);
        float4 o;
        o.x = (y[r][0] - mu) * rstd * gv.x + bv.x + xv.x;
        o.y = (y[r][1] - mu) * rstd * gv.y + bv.y + xv.y;
        o.z = (y[r][2] - mu) * rstd * gv.z + bv.z + xv.z;
        o.w = (y[r][3] - mu) * rstd * gv.w + bv.w + xv.w;
        *(float4*)(out + (size_t)(row0 + r) * HD + c) = o;
    }
}

// ---------------------------------------------------------------------------
// Launcher
// ---------------------------------------------------------------------------
extern "C" void kernel_launch(void* const* d_in, const int* in_sizes, int n_in,
                              void* d_out, int out_size)
{
    const float* X   = (const float*)d_in[0];
    const float* msk = (const float*)d_in[1];
    const float* emb = (const float*)d_in[2];
    const float* ltw = (const float*)d_in[3];
    const float* ltb = (const float*)d_in[4];
    const float* g1  = (const float*)d_in[5];
    const float* b1  = (const float*)d_in[6];
    const float* ftw = (const float*)d_in[7];
    const float* ftb = (const float*)d_in[8];
    const float* g2  = (const float*)d_in[9];
    const float* b2  = (const float*)d_in[10];
    float* out = (float*)d_out;

    float *bufA, *bufB;
    __half *A2, *Wt1, *Wt2;
    cudaGetSymbolAddress((void**)&bufA, g_bufA);
    cudaGetSymbolAddress((void**)&bufB, g_bufB);
    cudaGetSymbolAddress((void**)&A2,  g_A2);
    cudaGetSymbolAddress((void**)&Wt1, g_Wt1);
    cudaGetSymbolAddress((void**)&Wt2, g_Wt2);
    __half* Y1h = (__half*)bufA;              // fp16 Y1
    __half* Fh  = (__half*)bufB;              // fp16 F
    __half* Y2h = (__half*)bufB + (size_t)MROWS * HD / 2;  // fp16 Y2 (2nd half)

    cudaFuncSetAttribute((const void*)gemm_mma_kernel<float>,
                         cudaFuncAttributeMaxDynamicSharedMemorySize, GEMM_SMEM);
    cudaFuncSetAttribute((const void*)gemm_mma_kernel<__half>,
                         cudaFuncAttributeMaxDynamicSharedMemorySize, GEMM_SMEM);

    const dim3 ggrid(HD / BN, MROWS / (2 * BM));   // (8, 128) = 1024 CTAs

    // both weight transposes in one launch
    convW2_kernel<<<2 * (HD * HD) / 256, 256>>>(ltw, Wt1, ftw, Wt2);

    // 1) Y1 = X @ lt_w + lt_b   (fp16 out)
    convA_kernel<<<(MROWS * HD / 4) / 256, 256>>>(X, A2);
    gemm_mma_kernel<__half><<<ggrid, 128, GEMM_SMEM>>>(A2, Wt1, ltb, Y1h);
    // 2) F = fusion(LN1(Y1)) -> fp16, 4 rows/block, single reduction
    ln1_fusion_kernel<<<MROWS / RPB, 256>>>(Y1h, msk, emb, g1, b1, Fh);
    // 3) agg = multiscale(F), half2-vectorized, fp16 in/out -> A2
    multiscale_kernel<<<(BDIM * H2 * 32) / 256, 256>>>(
        (const __half2*)Fh, (__half2*)A2);
    // 4) Y2 = agg @ ft_w + ft_b  (fp16 out)
    gemm_mma_kernel<__half><<<ggrid, 128, GEMM_SMEM>>>(A2, Wt2, ftb, Y2h);
    // 5) out = LN2(Y2) + X
    ln2_res_kernel<<<MROWS / RPB, 256>>>(Y2h, X, g2, b2, out);
}

// round 16
// speedup vs baseline: 1.0562x; 1.0562x over previous
#include <cuda_runtime.h>
#include <cuda_fp16.h>
#include <math.h>
#include <stdint.h>

// Problem shape (fixed by setup_inputs)
#define MROWS 32768          // B*L
#define BDIM  8
#define LSEQ  4096
#define HD    1024
#define NL    4
#define NCHK  32             // HD / BK
#define NCHK2 64             // two tiles back-to-back
#define RPB   4              // rows per LN block

// GEMM tiling: CTA 128x128, 4 warps (2x2), warp tile 64x64, BK=32
#define BM 128
#define BN 128
#define BK 32
#define NSTAGE 3
#define ROWB 80                           // (32+8) fp16 = 80 bytes per row
#define A_STG (BM * ROWB)                 // 10240
#define B_STG (BN * ROWB)                 // 10240
#define STG   (A_STG + B_STG)             // 20480
#define GEMM_SMEM (NSTAGE * STG)          // 61440 (x3 CTAs = 184KB <= 228KB)

#define NCA_BLK ((MROWS * HD / 4) / 256)  // 32768 convA blocks
#define NCW_BLK (2 * (HD * HD) / 256)     // 8192 convW blocks

// ---------------------------------------------------------------------------
// Scratch (device globals: allocation-free)
// ---------------------------------------------------------------------------
__device__ float g_bufA[(size_t)MROWS * HD];     // low half reused as fp16 Y1
__device__ float g_bufB[(size_t)MROWS * HD];     // fp16 F / fp16 Y2
__device__ __align__(256) __half g_A2[(size_t)MROWS * HD];    // fp16 A
__device__ __align__(256) __half g_Wt1[(size_t)HD * HD];      // lt_w^T fp16
__device__ __align__(256) __half g_Wt2[(size_t)HD * HD];      // ft_w^T fp16

// ---------------------------------------------------------------------------
// PTX helpers (sm_80-class features only: cp.async, ldmatrix, mma.sync)
// ---------------------------------------------------------------------------
__device__ __forceinline__ uint32_t smem_to_u32(const void* p) {
    uint32_t a;
    asm("{ .reg .u64 t; cvta.to.shared.u64 t, %1; cvt.u32.u64 %0, t; }" : "=r"(a) : "l"(p));
    return a;
}
__device__ __forceinline__ void cp_async16(uint32_t dst, const void* src) {
    asm volatile("cp.async.cg.shared.global [%0], [%1], 16;\n" :: "r"(dst), "l"(src) : "memory");
}
#define CP_COMMIT() asm volatile("cp.async.commit_group;" ::: "memory")
#define CP_WAIT1()  asm volatile("cp.async.wait_group 1;" ::: "memory")

__device__ __forceinline__ void ldsm_x4(uint32_t (&r)[4], uint32_t addr) {
    asm volatile("ldmatrix.sync.aligned.m8n8.x4.shared.b16 {%0,%1,%2,%3}, [%4];"
        : "=r"(r[0]), "=r"(r[1]), "=r"(r[2]), "=r"(r[3]) : "r"(addr));
}
__device__ __forceinline__ void mma16816(float (&c)[4],
                                         const uint32_t (&a)[4],
                                         uint32_t b0, uint32_t b1) {
    asm volatile(
        "mma.sync.aligned.m16n8k16.row.col.f32.f16.f16.f32 "
        "{%0,%1,%2,%3}, {%4,%5,%6,%7}, {%8,%9}, {%0,%1,%2,%3};"
        : "+f"(c[0]), "+f"(c[1]), "+f"(c[2]), "+f"(c[3])
        : "r"(a[0]), "r"(a[1]), "r"(a[2]), "r"(a[3]), "r"(b0), "r"(b1));
}

__device__ __forceinline__ float warp_sum(float v) {
    #pragma unroll
    for (int o = 16; o > 0; o >>= 1) v += __shfl_xor_sync(0xffffffffu, v, o);
    return v;
}

// N simultaneous block-wide sums with ONE store+barrier round (256 thr, 8 warps)
template <int N>
__device__ __forceinline__ void blk_reduceN(float (&v)[N], float* sbuf)
{
    #pragma unroll
    for (int k = 0; k < N; ++k) v[k] = warp_sum(v[k]);
    const int lane = threadIdx.x & 31, w = threadIdx.x >> 5;
    if (lane == 0) {
        #pragma unroll
        for (int k = 0; k < N; ++k) sbuf[k * 8 + w] = v[k];
    }
    __syncthreads();
    if (threadIdx.x < 8 * N) {
        float x = sbuf[threadIdx.x];
        x += __shfl_xor_sync(0xffffffffu, x, 4);
        x += __shfl_xor_sync(0xffffffffu, x, 2);
        x += __shfl_xor_sync(0xffffffffu, x, 1);
        if ((threadIdx.x & 7) == 0) sbuf[8 * N + (threadIdx.x >> 3)] = x;
    }
    __syncthreads();
    #pragma unroll
    for (int k = 0; k < N; ++k) v[k] = sbuf[8 * N + k];
}

// ---------------------------------------------------------------------------
// Fused conversions: convA (X fp32 -> A2 fp16) + both weight transposes
// ---------------------------------------------------------------------------
__global__ __launch_bounds__(256) void conv_all_kernel(
    const float* __restrict__ A, __half* __restrict__ A2,
    const float* __restrict__ W1, __half* __restrict__ Wt1,
    const float* __restrict__ W2, __half* __restrict__ Wt2)
{
    if (blockIdx.x < NCA_BLK) {
        const size_t i = (size_t)blockIdx.x * 256 + threadIdx.x;
        const float4 v = *(const float4*)(A + i * 4);
        __half h[4];
        h[0] = __float2half_rn(v.x); h[1] = __float2half_rn(v.y);
        h[2] = __float2half_rn(v.z); h[3] = __float2half_rn(v.w);
        ((unsigned long long*)A2)[i] = *(const unsigned long long*)h;
    } else {
        const int bx = blockIdx.x - NCA_BLK;
        const int which = bx >= NCW_BLK / 2;
        const int idx = (bx - which * (NCW_BLK / 2)) * 256 + threadIdx.x;
        const int n = idx & (HD - 1);
        const int k = idx >> 10;
        const float* W = which ? W2 : W1;
        __half* Wt = which ? Wt2 : Wt1;
        Wt[(size_t)n * HD + k] = __float2half_rn(W[(size_t)k * HD + n]);
    }
}

// ---------------------------------------------------------------------------
// mma.sync GEMM (UNCHANGED): 2 M-tiles per CTA, seamless 64-chunk pipeline,
// CTA 128x128, 4 warps, 64x64 warp tiles, 3 stages, 3 CTAs/SM.
// ---------------------------------------------------------------------------
template <typename OutT>
__global__ __launch_bounds__(128, 3) void gemm_mma_kernel(
    const __half* __restrict__ A2,
    const __half* __restrict__ Wt,
    const float* __restrict__ bias,
    OutT* __restrict__ C)
{
    extern __shared__ char smem_raw[];
    const uint32_t sbase = smem_to_u32(smem_raw);

    const int tid = threadIdx.x;
    const int wid = tid >> 5;
    const int lane = tid & 31;
    const int m_base = blockIdx.y * (2 * BM);
    const int n0 = blockIdx.x * BN;

    const int wm = (wid >> 1) * 64;
    const int wn = (wid & 1) * 64;

    const int lr = tid >> 2;
    const int lc = tid & 3;
    const __half* gB[4];
    #pragma unroll
    for (int j = 0; j < 4; ++j)
        gB[j] = Wt + (size_t)(n0 + lr + 32 * j) * HD + lc * 8;
    const __half* gA_t0 = A2 + (size_t)(m_base + lr) * HD + lc * 8;
    const __half* gA_t1 = gA_t0 + (size_t)BM * HD;

    const uint32_t sA_off = lr * ROWB + lc * 16;
    const uint32_t sB_off = A_STG + lr * ROWB + lc * 16;
    const uint32_t RSTEP32 = 32 * ROWB;
    const size_t   ARSTEP = (size_t)32 * HD;

    const int lrow = lane & 15;
    const int lkof = (lane >> 4) * 16;
    const uint32_t aAddrBase = sbase + (wm + lrow) * ROWB + lkof;
    const uint32_t bAddrBase = sbase + A_STG + (wn + lrow) * ROWB + lkof;

    const int g = lane >> 2;
    const int t = lane & 3;

    float acc[4][8][4];
    #pragma unroll
    for (int i = 0; i < 4; ++i)
        #pragma unroll
        for (int j = 0; j < 8; ++j)
            #pragma unroll
            for (int q = 0; q < 4; ++q) acc[i][j][q] = 0.0f;

    auto issue = [&](int q, int stage) {
        const uint32_t sb = sbase + stage * STG;
        const size_t go = (size_t)(q & 31) * BK;
        const __half* gA = (q < NCHK) ? gA_t0 : gA_t1;
        #pragma unroll
        for (int j = 0; j < 4; ++j) {
            cp_async16(sb + sA_off + j * RSTEP32, gA + j * ARSTEP + go);
            cp_async16(sb + sB_off + j * RSTEP32, gB[j] + go);
        }
    };

    issue(0, 0); CP_COMMIT();
    issue(1, 1); CP_COMMIT();

    int s_c = 0;
    int s_q = 2;
    #pragma unroll 1
    for (int kc = 0; kc < NCHK2; ++kc) {
        CP_WAIT1();
        __syncthreads();

        const int q = kc + 2;
        if (q < NCHK2) issue(q, s_q);
        CP_COMMIT();

        const uint32_t stg = s_c * STG;
        #pragma unroll
        for (int ks = 0; ks < 2; ++ks) {
            uint32_t a[4][4], b[4][4];
            const uint32_t kb = stg + ks * 32;
            #pragma unroll
            for (int i = 0; i < 4; ++i)
                ldsm_x4(a[i], aAddrBase + kb + i * (16 * ROWB));
            #pragma unroll
            for (int j = 0; j < 4; ++j)
                ldsm_x4(b[j], bAddrBase + kb + j * (16 * ROWB));
            #pragma unroll
            for (int i = 0; i < 4; ++i) {
                #pragma unroll
                for (int j = 0; j < 4; ++j) {
                    mma16816(acc[i][2 * j + 0], a[i], b[j][0], b[j][2]);
                    mma16816(acc[i][2 * j + 1], a[i], b[j][1], b[j][3]);
                }
            }
        }

        if ((kc & (NCHK - 1)) == NCHK - 1) {
            const int m0 = m_base + (kc >> 5) * BM;
            #pragma unroll
            for (int i = 0; i < 4; ++i) {
                const int row = m0 + wm + i * 16 + g;
                #pragma unroll
                for (int j = 0; j < 8; ++j) {
                    const int col = n0 + wn + j * 8 + t * 2;
                    const float b0 = bias[col], b1 = bias[col + 1];
                    const float v00 = acc[i][j][0] + b0, v01 = acc[i][j][1] + b1;
                    const float v10 = acc[i][j][2] + b0, v11 = acc[i][j][3] + b1;
                    if (sizeof(OutT) == 4) {
                        *(float2*)((float*)C + (size_t)row * HD + col) = make_float2(v00, v01);
                        *(float2*)((float*)C + (size_t)(row + 8) * HD + col) = make_float2(v10, v11);
                    } else {
                        *(__half2*)((__half*)C + (size_t)row * HD + col) = __floats2half2_rn(v00, v01);
                        *(__half2*)((__half*)C + (size_t)(row + 8) * HD + col) = __floats2half2_rn(v10, v11);
                    }
                    acc[i][j][0] = 0.f; acc[i][j][1] = 0.f;
                    acc[i][j][2] = 0.f; acc[i][j][3] = 0.f;
                }
            }
        }

        if (++s_c == NSTAGE) s_c = 0;
        if (++s_q == NSTAGE) s_q = 0;
    }
}

// ---------------------------------------------------------------------------
// LN1 + hierarchical fusion: 4 rows per block (round-13 structure),
// fast transcendentals (__expf / __fdividef).
// ---------------------------------------------------------------------------
__global__ __launch_bounds__(256) void ln1_fusion_kernel(
    const __half* __restrict__ Y, const float* __restrict__ masks,
    const float* __restrict__ emb,
    const float* __restrict__ g, const float* __restrict__ bvec,
    __half* __restrict__ Fout)
{
    __shared__ float sbuf[144];

    const int row0 = blockIdx.x * RPB;
    const int c = threadIdx.x * 4;

    const float4 gv = __ldg((const float4*)(g + c));
    const float4 bv = __ldg((const float4*)(bvec + c));
    const float4 e0 = __ldg((const float4*)(emb + 0 * HD + c));
    const float4 e1 = __ldg((const float4*)(emb + 1 * HD + c));
    const float4 e2 = __ldg((const float4*)(emb + 2 * HD + c));
    const float4 e3 = __ldg((const float4*)(emb + 3 * HD + c));

    // load 4 rows, accumulate sums
    float y[RPB][4];
    float v8[8];
    #pragma unroll
    for (int r = 0; r < RPB; ++r) {
        const uint2 yraw = *(const uint2*)(Y + (size_t)(row0 + r) * HD + c);
        const float2 ya = __half22float2(*(const __half2*)&yraw.x);
        const float2 yb = __half22float2(*(const __half2*)&yraw.y);
        y[r][0] = ya.x; y[r][1] = ya.y; y[r][2] = yb.x; y[r][3] = yb.y;
        v8[r]       = ya.x + ya.y + yb.x + yb.y;
        v8[RPB + r] = ya.x * ya.x + ya.y * ya.y + yb.x * yb.x + yb.y * yb.y;
    }
    blk_reduceN<8>(v8, sbuf);

    // LN per row (overwrite y with t), accumulate 16 score partials
    float v16[16];
    #pragma unroll
    for (int r = 0; r < RPB; ++r) {
        const float mu   = v8[r] * (1.0f / HD);
        const float var  = v8[RPB + r] * (1.0f / HD) - mu * mu;
        const float rstd = rsqrtf(var + 1e-5f);
        y[r][0] = (y[r][0] - mu) * rstd * gv.x + bv.x;
        y[r][1] = (y[r][1] - mu) * rstd * gv.y + bv.y;
        y[r][2] = (y[r][2] - mu) * rstd * gv.z + bv.z;
        y[r][3] = (y[r][3] - mu) * rstd * gv.w + bv.w;
        v16[r * 4 + 0] = y[r][0] * e0.x + y[r][1] * e0.y + y[r][2] * e0.z + y[r][3] * e0.w;
        v16[r * 4 + 1] = y[r][0] * e1.x + y[r][1] * e1.y + y[r][2] * e1.z + y[r][3] * e1.w;
        v16[r * 4 + 2] = y[r][0] * e2.x + y[r][1] * e2.y + y[r][2] * e2.z + y[r][3] * e2.w;
        v16[r * 4 + 3] = y[r][0] * e3.x + y[r][1] * e3.y + y[r][2] * e3.z + y[r][3] * e3.w;
    }
    blk_reduceN<16>(v16, sbuf);

    // per-row epilogue (fast exp / fast divide)
    #pragma unroll
    for (int r = 0; r < RPB; ++r) {
        const float sc0 = v16[r * 4 + 0], sc1 = v16[r * 4 + 1];
        const float sc2 = v16[r * 4 + 2], sc3 = v16[r * 4 + 3];
        const float4 mk = __ldg((const float4*)(masks + (size_t)(row0 + r) * 4));
        const float wn0 = (mk.x > 0.5f) ? __expf(sc0) : 0.0f;
        const float wn1 = (mk.y > 0.5f) ? __expf(sc1) : 0.0f;
        const float wn2 = (mk.z > 0.5f) ? __expf(sc2) : 0.0f;
        const float wn3 = (mk.w > 0.5f) ? __expf(sc3) : 0.0f;
        const float tot = wn0 + wn1 + wn2 + wn3;
        const float inv = (tot > 1e-8f) ? __fdividef(1.0f, tot) : 1.0f;
        const float q0 = wn0 * inv, q1 = wn1 * inv, q2 = wn2 * inv, q3 = wn3 * inv;

        // gate: dot(fused, t) = sum_n q_n * sc_n  (exact identity)
        const float gsum = q0 * sc0 + q1 * sc1 + q2 * sc2 + q3 * sc3;
        const float gate = __fdividef(1.0f, 1.0f + __expf(-gsum * (1.0f / HD)));
        const float og = 1.0f - gate;

        const float f0 = q0 * e0.x + q1 * e1.x + q2 * e2.x + q3 * e3.x;
        const float f1 = q0 * e0.y + q1 * e1.y + q2 * e2.y + q3 * e3.y;
        const float f2 = q0 * e0.z + q1 * e1.z + q2 * e2.z + q3 * e3.z;
        const float f3 = q0 * e0.w + q1 * e1.w + q2 * e2.w + q3 * e3.w;

        const __half2 h01 = __floats2half2_rn(gate * f0 + og * y[r][0],
                                              gate * f1 + og * y[r][1]);
        const __half2 h23 = __floats2half2_rn(gate * f2 + og * y[r][2],
                                              gate * f3 + og * y[r][3]);
        __half2 hv[2] = {h01, h23};
        *(uint2*)(Fout + (size_t)(row0 + r) * HD + c) = *(uint2*)hv;
    }
}

// ---------------------------------------------------------------------------
// Multi-scale windowed means along L, __half2 vectorized (one thread per h-pair)
// ---------------------------------------------------------------------------
#define H2 512   // HD / 2

__global__ __launch_bounds__(256) void multiscale_kernel(
    const __half2* __restrict__ F2, __half2* __restrict__ O2)
{
    const int L = LSEQ;
    const int SL = 128;

    const int gtid = blockIdx.x * 256 + threadIdx.x;
    const int h = gtid & (H2 - 1);
    const int rest = gtid >> 9;
    const int b = rest & 7;
    const int strip = rest >> 3;
    const int s0 = strip * SL;

    const __half2* base = F2 + (size_t)b * L * H2 + h;
    __half2* oA = O2 + (size_t)b * L * H2 + h;

    const float SW3  = (float)(1.0 / (1.0 + 1.0986122886681098));
    const float SW7  = (float)(1.0 / (1.0 + 1.9459101090932196));
    const float SW15 = (float)(1.0 / (1.0 + 2.7080502011022101));

    if (strip > 0 && strip < 31) {
        float2 ring[16];
        #pragma unroll
        for (int j = -8; j <= 6; ++j)
            ring[j & 15] = __half22float2(base[(size_t)(s0 + j) * H2]);

        float2 s3 = {0.f, 0.f}, s7 = {0.f, 0.f}, s15 = {0.f, 0.f};
        #pragma unroll
        for (int j = -8; j <= 6; ++j) {
            const float2 v = ring[j & 15];
            const int d = j + 1;
            if (d >= -7 && d <= 7) { s15.x += v.x; s15.y += v.y; }
            if (d >= -3 && d <= 3) { s7.x  += v.x; s7.y  += v.y; }
            if (d >= -1 && d <= 1) { s3.x  += v.x; s3.y  += v.y; }
        }

        const float w3 = SW3 * (1.0f / 3.0f);
        const float w7 = SW7 * (1.0f / 7.0f);
        const float w15 = SW15 * (1.0f / 15.0f);

        #pragma unroll 1
        for (int cch = 0; cch < SL; cch += 16) {
            #pragma unroll
            for (int i = 0; i < 16; ++i) {
                const int l = s0 + cch + i;
                const float2 nv = __half22float2(base[(size_t)(l + 7) * H2]);
                ring[(i + 7) & 15] = nv;
                s3.x  += ring[(i + 1) & 15].x - ring[(i - 2) & 15].x;
                s3.y  += ring[(i + 1) & 15].y - ring[(i - 2) & 15].y;
                s7.x  += ring[(i + 3) & 15].x - ring[(i - 4) & 15].x;
                s7.y  += ring[(i + 3) & 15].y - ring[(i - 4) & 15].y;
                s15.x += nv.x               - ring[(i - 8) & 15].x;
                s15.y += nv.y               - ring[(i - 8) & 15].y;
                const float2 s1 = ring[i & 15];
                const float ox = s1.x + s3.x * w3 + s7.x * w7 + s15.x * w15;
                const float oy = s1.y + s3.y * w3 + s7.y * w7 + s15.y * w15;
                oA[(size_t)l * H2] = __floats2half2_rn(ox, oy);
            }
        }
    } else {
        for (int l = s0; l < s0 + SL; ++l) {
            float2 s3 = {0.f, 0.f}, s7 = {0.f, 0.f}, s15 = {0.f, 0.f};
            #pragma unroll
            for (int j = -7; j <= 7; ++j) {
                const int p = l + j;
                float2 v = {0.f, 0.f};
                if (p >= 0 && p < L) v = __half22float2(base[(size_t)p * H2]);
                s15.x += v.x; s15.y += v.y;
                if (j >= -3 && j <= 3) { s7.x += v.x; s7.y += v.y; }
                if (j >= -1 && j <= 1) { s3.x += v.x; s3.y += v.y; }
            }
            const float2 s1 = __half22float2(base[(size_t)l * H2]);
            const float c3  = 1.0f / (float)(min(l + 2, L) - max(l - 1, 0));
            const float c7  = 1.0f / (float)(min(l + 4, L) - max(l - 3, 0));
            const float c15 = 1.0f / (float)(min(l + 8, L) - max(l - 7, 0));
            const float ox = s1.x + SW3 * s3.x * c3 + SW7 * s7.x * c7 + SW15 * s15.x * c15;
            const float oy = s1.y + SW3 * s3.y * c3 + SW7 * s7.y * c7 + SW15 * s15.y * c15;
            oA[(size_t)l * H2] = __floats2half2_rn(ox, oy);
        }
    }
}

// ---------------------------------------------------------------------------
// LN2 + residual: 4 rows per block, batched dual reductions
// ---------------------------------------------------------------------------
__global__ __launch_bounds__(256) void ln2_res_kernel(
    const __half* __restrict__ Y, const float* __restrict__ X,
    const float* __restrict__ g, const float* __restrict__ bvec,
    float* __restrict__ out)
{
    __shared__ float sbuf[72];
    const int row0 = blockIdx.x * RPB;
    const int c = threadIdx.x * 4;

    const float4 gv = __ldg((const float4*)(g + c));
    const float4 bv = __ldg((const float4*)(bvec + c));

    float y[RPB][4];
    float v8[8];
    #pragma unroll
    for (int r = 0; r < RPB; ++r) {
        const uint2 yraw = *(const uint2*)(Y + (size_t)(row0 + r) * HD + c);
        const float2 ya = __half22float2(*(const __half2*)&yraw.x);
        const float2 yb = __half22float2(*(const __half2*)&yraw.y);
        y[r][0] = ya.x; y[r][1] = ya.y; y[r][2] = yb.x; y[r][3] = yb.y;
        v8[r]       = ya.x + ya.y + yb.x + yb.y;
        v8[RPB + r] = ya.x * ya.x + ya.y * ya.y + yb.x * yb.x + yb.y * yb.y;
    }
    blk_reduceN<8>(v8, sbuf);

    #pragma unroll
    for (int r = 0; r < RPB; ++r) {
        const float mu   = v8[r] * (1.0f / HD);
        const float var  = v8[RPB + r] * (1.0f / HD) - mu * mu;
        const float rstd = rsqrtf(var + 1e-5f);
        const float4 xv = *(const float4*)(X + (size_t)(row0 + r) * HD + c);
        float4 o;
        o.x = (y[r][0] - mu) * rstd * gv.x + bv.x + xv.x;
        o.y = (y[r][1] - mu) * rstd * gv.y + bv.y + xv.y;
        o.z = (y[r][2] - mu) * rstd * gv.z + bv.z + xv.z;
        o.w = (y[r][3] - mu) * rstd * gv.w + bv.w + xv.w;
        *(float4*)(out + (size_t)(row0 + r) * HD + c) = o;
    }
}

// ---------------------------------------------------------------------------
// Launcher
// ---------------------------------------------------------------------------
extern "C" void kernel_launch(void* const* d_in, const int* in_sizes, int n_in,
                              void* d_out, int out_size)
{
    const float* X   = (const float*)d_in[0];
    const float* msk = (const float*)d_in[1];
    const float* emb = (const float*)d_in[2];
    const float* ltw = (const float*)d_in[3];
    const float* ltb = (const float*)d_in[4];
    const float* g1  = (const float*)d_in[5];
    const float* b1  = (const float*)d_in[6];
    const float* ftw = (const float*)d_in[7];
    const float* ftb = (const float*)d_in[8];
    const float* g2  = (const float*)d_in[9];
    const float* b2  = (const float*)d_in[10];
    float* out = (float*)d_out;

    float *bufA, *bufB;
    __half *A2, *Wt1, *Wt2;
    cudaGetSymbolAddress((void**)&bufA, g_bufA);
    cudaGetSymbolAddress((void**)&bufB, g_bufB);
    cudaGetSymbolAddress((void**)&A2,  g_A2);
    cudaGetSymbolAddress((void**)&Wt1, g_Wt1);
    cudaGetSymbolAddress((void**)&Wt2, g_Wt2);
    __half* Y1h = (__half*)bufA;              // fp16 Y1
    __half* Fh  = (__half*)bufB;              // fp16 F
    __half* Y2h = (__half*)bufB + (size_t)MROWS * HD / 2;  // fp16 Y2 (2nd half)

    cudaFuncSetAttribute((const void*)gemm_mma_kernel<float>,
                         cudaFuncAttributeMaxDynamicSharedMemorySize, GEMM_SMEM);
    cudaFuncSetAttribute((const void*)gemm_mma_kernel<__half>,
                         cudaFuncAttributeMaxDynamicSharedMemorySize, GEMM_SMEM);

    const dim3 ggrid(HD / BN, MROWS / (2 * BM));   // (8, 128) = 1024 CTAs

    // all input conversions in ONE launch (convA + both weight transposes)
    conv_all_kernel<<<NCA_BLK + NCW_BLK, 256>>>(X, A2, ltw, Wt1, ftw, Wt2);

    // 1) Y1 = X @ lt_w + lt_b   (fp16 out)
    gemm_mma_kernel<__half><<<ggrid, 128, GEMM_SMEM>>>(A2, Wt1, ltb, Y1h);
    // 2) F = fusion(LN1(Y1)) -> fp16, 4 rows/block
    ln1_fusion_kernel<<<MROWS / RPB, 256>>>(Y1h, msk, emb, g1, b1, Fh);
    // 3) agg = multiscale(F), half2-vectorized, fp16 in/out -> A2
    multiscale_kernel<<<(BDIM * H2 * 32) / 256, 256>>>(
        (const __half2*)Fh, (__half2*)A2);
    // 4) Y2 = agg @ ft_w + ft_b  (fp16 out)
    gemm_mma_kernel<__half><<<ggrid, 128, GEMM_SMEM>>>(A2, Wt2, ftb, Y2h);
    // 5) out = LN2(Y2) + X
    ln2_res_kernel<<<MROWS / RPB, 256>>>(Y2h, X, g2, b2, out);
}

// round 17
// speedup vs baseline: 1.0904x; 1.0324x over previous
#include <cuda_runtime.h>
#include <cuda_fp16.h>
#include <math.h>
#include <stdint.h>

// Problem shape (fixed by setup_inputs)
#define MROWS 32768          // B*L
#define BDIM  8
#define LSEQ  4096
#define HD    1024
#define NL    4
#define NCHK  32             // HD / BK
#define NCHK2 64             // two tiles back-to-back
#define RPB   4              // rows per LN block

// GEMM tiling: CTA 128x128, 4 warps (2x2), warp tile 64x64, BK=32
#define BM 128
#define BN 128
#define BK 32
#define NSTAGE 3
#define ROWB 80                           // (32+8) fp16 = 80 bytes per row
#define A_STG (BM * ROWB)                 // 10240
#define B_STG (BN * ROWB)                 // 10240
#define STG   (A_STG + B_STG)             // 20480
#define GEMM_SMEM (NSTAGE * STG)          // 61440 (x3 CTAs = 184KB <= 228KB)

#define NCA_BLK ((MROWS * HD / 4) / 256)  // 32768 convA blocks
#define NCW_BLK (2 * (HD * HD) / 256)     // 8192 convW blocks

// multiscale strip length (shorter => more parallelism)
#define MS_SL 64
#define MS_NSTRIP (LSEQ / MS_SL)          // 64

// ---------------------------------------------------------------------------
// Scratch (device globals: allocation-free)
// ---------------------------------------------------------------------------
__device__ float g_bufA[(size_t)MROWS * HD];     // low half reused as fp16 Y1
__device__ float g_bufB[(size_t)MROWS * HD];     // fp16 F / fp16 Y2
__device__ __align__(256) __half g_A2[(size_t)MROWS * HD];    // fp16 A
__device__ __align__(256) __half g_Wt1[(size_t)HD * HD];      // lt_w^T fp16
__device__ __align__(256) __half g_Wt2[(size_t)HD * HD];      // ft_w^T fp16

// ---------------------------------------------------------------------------
// PTX helpers (sm_80-class features only: cp.async, ldmatrix, mma.sync)
// ---------------------------------------------------------------------------
__device__ __forceinline__ uint32_t smem_to_u32(const void* p) {
    uint32_t a;
    asm("{ .reg .u64 t; cvta.to.shared.u64 t, %1; cvt.u32.u64 %0, t; }" : "=r"(a) : "l"(p));
    return a;
}
__device__ __forceinline__ void cp_async16(uint32_t dst, const void* src) {
    asm volatile("cp.async.cg.shared.global [%0], [%1], 16;\n" :: "r"(dst), "l"(src) : "memory");
}
#define CP_COMMIT() asm volatile("cp.async.commit_group;" ::: "memory")
#define CP_WAIT1()  asm volatile("cp.async.wait_group 1;" ::: "memory")

__device__ __forceinline__ void ldsm_x4(uint32_t (&r)[4], uint32_t addr) {
    asm volatile("ldmatrix.sync.aligned.m8n8.x4.shared.b16 {%0,%1,%2,%3}, [%4];"
        : "=r"(r[0]), "=r"(r[1]), "=r"(r[2]), "=r"(r[3]) : "r"(addr));
}
__device__ __forceinline__ void mma16816(float (&c)[4],
                                         const uint32_t (&a)[4],
                                         uint32_t b0, uint32_t b1) {
    asm volatile(
        "mma.sync.aligned.m16n8k16.row.col.f32.f16.f16.f32 "
        "{%0,%1,%2,%3}, {%4,%5,%6,%7}, {%8,%9}, {%0,%1,%2,%3};"
        : "+f"(c[0]), "+f"(c[1]), "+f"(c[2]), "+f"(c[3])
        : "r"(a[0]), "r"(a[1]), "r"(a[2]), "r"(a[3]), "r"(b0), "r"(b1));
}

__device__ __forceinline__ float warp_sum(float v) {
    #pragma unroll
    for (int o = 16; o > 0; o >>= 1) v += __shfl_xor_sync(0xffffffffu, v, o);
    return v;
}

// N simultaneous block-wide sums with ONE store+barrier round (256 thr, 8 warps)
template <int N>
__device__ __forceinline__ void blk_reduceN(float (&v)[N], float* sbuf)
{
    #pragma unroll
    for (int k = 0; k < N; ++k) v[k] = warp_sum(v[k]);
    const int lane = threadIdx.x & 31, w = threadIdx.x >> 5;
    if (lane == 0) {
        #pragma unroll
        for (int k = 0; k < N; ++k) sbuf[k * 8 + w] = v[k];
    }
    __syncthreads();
    if (threadIdx.x < 8 * N) {
        float x = sbuf[threadIdx.x];
        x += __shfl_xor_sync(0xffffffffu, x, 4);
        x += __shfl_xor_sync(0xffffffffu, x, 2);
        x += __shfl_xor_sync(0xffffffffu, x, 1);
        if ((threadIdx.x & 7) == 0) sbuf[8 * N + (threadIdx.x >> 3)] = x;
    }
    __syncthreads();
    #pragma unroll
    for (int k = 0; k < N; ++k) v[k] = sbuf[8 * N + k];
}

// ---------------------------------------------------------------------------
// Fused conversions: convA (X fp32 -> A2 fp16) + both weight transposes
// ---------------------------------------------------------------------------
__global__ __launch_bounds__(256) void conv_all_kernel(
    const float* __restrict__ A, __half* __restrict__ A2,
    const float* __restrict__ W1, __half* __restrict__ Wt1,
    const float* __restrict__ W2, __half* __restrict__ Wt2)
{
    if (blockIdx.x < NCA_BLK) {
        const size_t i = (size_t)blockIdx.x * 256 + threadIdx.x;
        const float4 v = *(const float4*)(A + i * 4);
        __half h[4];
        h[0] = __float2half_rn(v.x); h[1] = __float2half_rn(v.y);
        h[2] = __float2half_rn(v.z); h[3] = __float2half_rn(v.w);
        ((unsigned long long*)A2)[i] = *(const unsigned long long*)h;
    } else {
        const int bx = blockIdx.x - NCA_BLK;
        const int which = bx >= NCW_BLK / 2;
        const int idx = (bx - which * (NCW_BLK / 2)) * 256 + threadIdx.x;
        const int n = idx & (HD - 1);
        const int k = idx >> 10;
        const float* W = which ? W2 : W1;
        __half* Wt = which ? Wt2 : Wt1;
        Wt[(size_t)n * HD + k] = __float2half_rn(W[(size_t)k * HD + n]);
    }
}

// ---------------------------------------------------------------------------
// mma.sync GEMM (UNCHANGED): 2 M-tiles per CTA, seamless 64-chunk pipeline,
// CTA 128x128, 4 warps, 64x64 warp tiles, 3 stages, 3 CTAs/SM.
// ---------------------------------------------------------------------------
template <typename OutT>
__global__ __launch_bounds__(128, 3) void gemm_mma_kernel(
    const __half* __restrict__ A2,
    const __half* __restrict__ Wt,
    const float* __restrict__ bias,
    OutT* __restrict__ C)
{
    extern __shared__ char smem_raw[];
    const uint32_t sbase = smem_to_u32(smem_raw);

    const int tid = threadIdx.x;
    const int wid = tid >> 5;
    const int lane = tid & 31;
    const int m_base = blockIdx.y * (2 * BM);
    const int n0 = blockIdx.x * BN;

    const int wm = (wid >> 1) * 64;
    const int wn = (wid & 1) * 64;

    const int lr = tid >> 2;
    const int lc = tid & 3;
    const __half* gB[4];
    #pragma unroll
    for (int j = 0; j < 4; ++j)
        gB[j] = Wt + (size_t)(n0 + lr + 32 * j) * HD + lc * 8;
    const __half* gA_t0 = A2 + (size_t)(m_base + lr) * HD + lc * 8;
    const __half* gA_t1 = gA_t0 + (size_t)BM * HD;

    const uint32_t sA_off = lr * ROWB + lc * 16;
    const uint32_t sB_off = A_STG + lr * ROWB + lc * 16;
    const uint32_t RSTEP32 = 32 * ROWB;
    const size_t   ARSTEP = (size_t)32 * HD;

    const int lrow = lane & 15;
    const int lkof = (lane >> 4) * 16;
    const uint32_t aAddrBase = sbase + (wm + lrow) * ROWB + lkof;
    const uint32_t bAddrBase = sbase + A_STG + (wn + lrow) * ROWB + lkof;

    const int g = lane >> 2;
    const int t = lane & 3;

    float acc[4][8][4];
    #pragma unroll
    for (int i = 0; i < 4; ++i)
        #pragma unroll
        for (int j = 0; j < 8; ++j)
            #pragma unroll
            for (int q = 0; q < 4; ++q) acc[i][j][q] = 0.0f;

    auto issue = [&](int q, int stage) {
        const uint32_t sb = sbase + stage * STG;
        const size_t go = (size_t)(q & 31) * BK;
        const __half* gA = (q < NCHK) ? gA_t0 : gA_t1;
        #pragma unroll
        for (int j = 0; j < 4; ++j) {
            cp_async16(sb + sA_off + j * RSTEP32, gA + j * ARSTEP + go);
            cp_async16(sb + sB_off + j * RSTEP32, gB[j] + go);
        }
    };

    issue(0, 0); CP_COMMIT();
    issue(1, 1); CP_COMMIT();

    int s_c = 0;
    int s_q = 2;
    #pragma unroll 1
    for (int kc = 0; kc < NCHK2; ++kc) {
        CP_WAIT1();
        __syncthreads();

        const int q = kc + 2;
        if (q < NCHK2) issue(q, s_q);
        CP_COMMIT();

        const uint32_t stg = s_c * STG;
        #pragma unroll
        for (int ks = 0; ks < 2; ++ks) {
            uint32_t a[4][4], b[4][4];
            const uint32_t kb = stg + ks * 32;
            #pragma unroll
            for (int i = 0; i < 4; ++i)
                ldsm_x4(a[i], aAddrBase + kb + i * (16 * ROWB));
            #pragma unroll
            for (int j = 0; j < 4; ++j)
                ldsm_x4(b[j], bAddrBase + kb + j * (16 * ROWB));
            #pragma unroll
            for (int i = 0; i < 4; ++i) {
                #pragma unroll
                for (int j = 0; j < 4; ++j) {
                    mma16816(acc[i][2 * j + 0], a[i], b[j][0], b[j][2]);
                    mma16816(acc[i][2 * j + 1], a[i], b[j][1], b[j][3]);
                }
            }
        }

        if ((kc & (NCHK - 1)) == NCHK - 1) {
            const int m0 = m_base + (kc >> 5) * BM;
            #pragma unroll
            for (int i = 0; i < 4; ++i) {
                const int row = m0 + wm + i * 16 + g;
                #pragma unroll
                for (int j = 0; j < 8; ++j) {
                    const int col = n0 + wn + j * 8 + t * 2;
                    const float b0 = bias[col], b1 = bias[col + 1];
                    const float v00 = acc[i][j][0] + b0, v01 = acc[i][j][1] + b1;
                    const float v10 = acc[i][j][2] + b0, v11 = acc[i][j][3] + b1;
                    if (sizeof(OutT) == 4) {
                        *(float2*)((float*)C + (size_t)row * HD + col) = make_float2(v00, v01);
                        *(float2*)((float*)C + (size_t)(row + 8) * HD + col) = make_float2(v10, v11);
                    } else {
                        *(__half2*)((__half*)C + (size_t)row * HD + col) = __floats2half2_rn(v00, v01);
                        *(__half2*)((__half*)C + (size_t)(row + 8) * HD + col) = __floats2half2_rn(v10, v11);
                    }
                    acc[i][j][0] = 0.f; acc[i][j][1] = 0.f;
                    acc[i][j][2] = 0.f; acc[i][j][3] = 0.f;
                }
            }
        }

        if (++s_c == NSTAGE) s_c = 0;
        if (++s_q == NSTAGE) s_q = 0;
    }
}

// ---------------------------------------------------------------------------
// LN1 + hierarchical fusion: 4 rows per block, fast transcendentals.
// ---------------------------------------------------------------------------
__global__ __launch_bounds__(256) void ln1_fusion_kernel(
    const __half* __restrict__ Y, const float* __restrict__ masks,
    const float* __restrict__ emb,
    const float* __restrict__ g, const float* __restrict__ bvec,
    __half* __restrict__ Fout)
{
    __shared__ float sbuf[144];

    const int row0 = blockIdx.x * RPB;
    const int c = threadIdx.x * 4;

    const float4 gv = __ldg((const float4*)(g + c));
    const float4 bv = __ldg((const float4*)(bvec + c));
    const float4 e0 = __ldg((const float4*)(emb + 0 * HD + c));
    const float4 e1 = __ldg((const float4*)(emb + 1 * HD + c));
    const float4 e2 = __ldg((const float4*)(emb + 2 * HD + c));
    const float4 e3 = __ldg((const float4*)(emb + 3 * HD + c));

    float y[RPB][4];
    float v8[8];
    #pragma unroll
    for (int r = 0; r < RPB; ++r) {
        const uint2 yraw = *(const uint2*)(Y + (size_t)(row0 + r) * HD + c);
        const float2 ya = __half22float2(*(const __half2*)&yraw.x);
        const float2 yb = __half22float2(*(const __half2*)&yraw.y);
        y[r][0] = ya.x; y[r][1] = ya.y; y[r][2] = yb.x; y[r][3] = yb.y;
        v8[r]       = ya.x + ya.y + yb.x + yb.y;
        v8[RPB + r] = ya.x * ya.x + ya.y * ya.y + yb.x * yb.x + yb.y * yb.y;
    }
    blk_reduceN<8>(v8, sbuf);

    float v16[16];
    #pragma unroll
    for (int r = 0; r < RPB; ++r) {
        const float mu   = v8[r] * (1.0f / HD);
        const float var  = v8[RPB + r] * (1.0f / HD) - mu * mu;
        const float rstd = rsqrtf(var + 1e-5f);
        y[r][0] = (y[r][0] - mu) * rstd * gv.x + bv.x;
        y[r][1] = (y[r][1] - mu) * rstd * gv.y + bv.y;
        y[r][2] = (y[r][2] - mu) * rstd * gv.z + bv.z;
        y[r][3] = (y[r][3] - mu) * rstd * gv.w + bv.w;
        v16[r * 4 + 0] = y[r][0] * e0.x + y[r][1] * e0.y + y[r][2] * e0.z + y[r][3] * e0.w;
        v16[r * 4 + 1] = y[r][0] * e1.x + y[r][1] * e1.y + y[r][2] * e1.z + y[r][3] * e1.w;
        v16[r * 4 + 2] = y[r][0] * e2.x + y[r][1] * e2.y + y[r][2] * e2.z + y[r][3] * e2.w;
        v16[r * 4 + 3] = y[r][0] * e3.x + y[r][1] * e3.y + y[r][2] * e3.z + y[r][3] * e3.w;
    }
    blk_reduceN<16>(v16, sbuf);

    #pragma unroll
    for (int r = 0; r < RPB; ++r) {
        const float sc0 = v16[r * 4 + 0], sc1 = v16[r * 4 + 1];
        const float sc2 = v16[r * 4 + 2], sc3 = v16[r * 4 + 3];
        const float4 mk = __ldg((const float4*)(masks + (size_t)(row0 + r) * 4));
        const float wn0 = (mk.x > 0.5f) ? __expf(sc0) : 0.0f;
        const float wn1 = (mk.y > 0.5f) ? __expf(sc1) : 0.0f;
        const float wn2 = (mk.z > 0.5f) ? __expf(sc2) : 0.0f;
        const float wn3 = (mk.w > 0.5f) ? __expf(sc3) : 0.0f;
        const float tot = wn0 + wn1 + wn2 + wn3;
        const float inv = (tot > 1e-8f) ? __fdividef(1.0f, tot) : 1.0f;
        const float q0 = wn0 * inv, q1 = wn1 * inv, q2 = wn2 * inv, q3 = wn3 * inv;

        const float gsum = q0 * sc0 + q1 * sc1 + q2 * sc2 + q3 * sc3;
        const float gate = __fdividef(1.0f, 1.0f + __expf(-gsum * (1.0f / HD)));
        const float og = 1.0f - gate;

        const float f0 = q0 * e0.x + q1 * e1.x + q2 * e2.x + q3 * e3.x;
        const float f1 = q0 * e0.y + q1 * e1.y + q2 * e2.y + q3 * e3.y;
        const float f2 = q0 * e0.z + q1 * e1.z + q2 * e2.z + q3 * e3.z;
        const float f3 = q0 * e0.w + q1 * e1.w + q2 * e2.w + q3 * e3.w;

        const __half2 h01 = __floats2half2_rn(gate * f0 + og * y[r][0],
                                              gate * f1 + og * y[r][1]);
        const __half2 h23 = __floats2half2_rn(gate * f2 + og * y[r][2],
                                              gate * f3 + og * y[r][3]);
        __half2 hv[2] = {h01, h23};
        *(uint2*)(Fout + (size_t)(row0 + r) * HD + c) = *(uint2*)hv;
    }
}

// ---------------------------------------------------------------------------
// Multi-scale windowed means along L, __half2 vectorized, SL=64 strips
// (doubled grid for latency coverage)
// ---------------------------------------------------------------------------
#define H2 512   // HD / 2

__global__ __launch_bounds__(256) void multiscale_kernel(
    const __half2* __restrict__ F2, __half2* __restrict__ O2)
{
    const int L = LSEQ;
    const int SL = MS_SL;

    const int gtid = blockIdx.x * 256 + threadIdx.x;
    const int h = gtid & (H2 - 1);
    const int rest = gtid >> 9;
    const int b = rest & 7;
    const int strip = rest >> 3;          // 0..MS_NSTRIP-1
    const int s0 = strip * SL;

    const __half2* base = F2 + (size_t)b * L * H2 + h;
    __half2* oA = O2 + (size_t)b * L * H2 + h;

    const float SW3  = (float)(1.0 / (1.0 + 1.0986122886681098));
    const float SW7  = (float)(1.0 / (1.0 + 1.9459101090932196));
    const float SW15 = (float)(1.0 / (1.0 + 2.7080502011022101));

    if (strip > 0 && strip < MS_NSTRIP - 1) {
        float2 ring[16];
        #pragma unroll
        for (int j = -8; j <= 6; ++j)
            ring[j & 15] = __half22float2(base[(size_t)(s0 + j) * H2]);

        float2 s3 = {0.f, 0.f}, s7 = {0.f, 0.f}, s15 = {0.f, 0.f};
        #pragma unroll
        for (int j = -8; j <= 6; ++j) {
            const float2 v = ring[j & 15];
            const int d = j + 1;
            if (d >= -7 && d <= 7) { s15.x += v.x; s15.y += v.y; }
            if (d >= -3 && d <= 3) { s7.x  += v.x; s7.y  += v.y; }
            if (d >= -1 && d <= 1) { s3.x  += v.x; s3.y  += v.y; }
        }

        const float w3 = SW3 * (1.0f / 3.0f);
        const float w7 = SW7 * (1.0f / 7.0f);
        const float w15 = SW15 * (1.0f / 15.0f);

        #pragma unroll 1
        for (int cch = 0; cch < SL; cch += 16) {
            #pragma unroll
            for (int i = 0; i < 16; ++i) {
                const int l = s0 + cch + i;
                const float2 nv = __half22float2(base[(size_t)(l + 7) * H2]);
                ring[(i + 7) & 15] = nv;
                s3.x  += ring[(i + 1) & 15].x - ring[(i - 2) & 15].x;
                s3.y  += ring[(i + 1) & 15].y - ring[(i - 2) & 15].y;
                s7.x  += ring[(i + 3) & 15].x - ring[(i - 4) & 15].x;
                s7.y  += ring[(i + 3) & 15].y - ring[(i - 4) & 15].y;
                s15.x += nv.x               - ring[(i - 8) & 15].x;
                s15.y += nv.y               - ring[(i - 8) & 15].y;
                const float2 s1 = ring[i & 15];
                const float ox = s1.x + s3.x * w3 + s7.x * w7 + s15.x * w15;
                const float oy = s1.y + s3.y * w3 + s7.y * w7 + s15.y * w15;
                oA[(size_t)l * H2] = __floats2half2_rn(ox, oy);
            }
        }
    } else {
        for (int l = s0; l < s0 + SL; ++l) {
            float2 s3 = {0.f, 0.f}, s7 = {0.f, 0.f}, s15 = {0.f, 0.f};
            #pragma unroll
            for (int j = -7; j <= 7; ++j) {
                const int p = l + j;
                float2 v = {0.f, 0.f};
                if (p >= 0 && p < L) v = __half22float2(base[(size_t)p * H2]);
                s15.x += v.x; s15.y += v.y;
                if (j >= -3 && j <= 3) { s7.x += v.x; s7.y += v.y; }
                if (j >= -1 && j <= 1) { s3.x += v.x; s3.y += v.y; }
            }
            const float2 s1 = __half22float2(base[(size_t)l * H2]);
            const float c3  = 1.0f / (float)(min(l + 2, L) - max(l - 1, 0));
            const float c7  = 1.0f / (float)(min(l + 4, L) - max(l - 3, 0));
            const float c15 = 1.0f / (float)(min(l + 8, L) - max(l - 7, 0));
            const float ox = s1.x + SW3 * s3.x * c3 + SW7 * s7.x * c7 + SW15 * s15.x * c15;
            const float oy = s1.y + SW3 * s3.y * c3 + SW7 * s7.y * c7 + SW15 * s15.y * c15;
            oA[(size_t)l * H2] = __floats2half2_rn(ox, oy);
        }
    }
}

// ---------------------------------------------------------------------------
// LN2 + residual: 4 rows per block, batched dual reductions
// ---------------------------------------------------------------------------
__global__ __launch_bounds__(256) void ln2_res_kernel(
    const __half* __restrict__ Y, const float* __restrict__ X,
    const float* __restrict__ g, const float* __restrict__ bvec,
    float* __restrict__ out)
{
    __shared__ float sbuf[72];
    const int row0 = blockIdx.x * RPB;
    const int c = threadIdx.x * 4;

    const float4 gv = __ldg((const float4*)(g + c));
    const float4 bv = __ldg((const float4*)(bvec + c));

    float y[RPB][4];
    float v8[8];
    #pragma unroll
    for (int r = 0; r < RPB; ++r) {
        const uint2 yraw = *(const uint2*)(Y + (size_t)(row0 + r) * HD + c);
        const float2 ya = __half22float2(*(const __half2*)&yraw.x);
        const float2 yb = __half22float2(*(const __half2*)&yraw.y);
        y[r][0] = ya.x; y[r][1] = ya.y; y[r][2] = yb.x; y[r][3] = yb.y;
        v8[r]       = ya.x + ya.y + yb.x + yb.y;
        v8[RPB + r] = ya.x * ya.x + ya.y * ya.y + yb.x * yb.x + yb.y * yb.y;
    }
    blk_reduceN<8>(v8, sbuf);

    #pragma unroll
    for (int r = 0; r < RPB; ++r) {
        const float mu   = v8[r] * (1.0f / HD);
        const float var  = v8[RPB + r] * (1.0f / HD) - mu * mu;
        const float rstd = rsqrtf(var + 1e-5f);
        const float4 xv = *(const float4*)(X + (size_t)(row0 + r) * HD + c);
        float4 o;
        o.x = (y[r][0] - mu) * rstd * gv.x + bv.x + xv.x;
        o.y = (y[r][1] - mu) * rstd * gv.y + bv.y + xv.y;
        o.z = (y[r][2] - mu) * rstd * gv.z + bv.z + xv.z;
        o.w = (y[r][3] - mu) * rstd * gv.w + bv.w + xv.w;
        *(float4*)(out + (size_t)(row0 + r) * HD + c) = o;
    }
}

// ---------------------------------------------------------------------------
// Launcher
// ---------------------------------------------------------------------------
extern "C" void kernel_launch(void* const* d_in, const int* in_sizes, int n_in,
                              void* d_out, int out_size)
{
    const float* X   = (const float*)d_in[0];
    const float* msk = (const float*)d_in[1];
    const float* emb = (const float*)d_in[2];
    const float* ltw = (const float*)d_in[3];
    const float* ltb = (const float*)d_in[4];
    const float* g1  = (const float*)d_in[5];
    const float* b1  = (const float*)d_in[6];
    const float* ftw = (const float*)d_in[7];
    const float* ftb = (const float*)d_in[8];
    const float* g2  = (const float*)d_in[9];
    const float* b2  = (const float*)d_in[10];
    float* out = (float*)d_out;

    float *bufA, *bufB;
    __half *A2, *Wt1, *Wt2;
    cudaGetSymbolAddress((void**)&bufA, g_bufA);
    cudaGetSymbolAddress((void**)&bufB, g_bufB);
    cudaGetSymbolAddress((void**)&A2,  g_A2);
    cudaGetSymbolAddress((void**)&Wt1, g_Wt1);
    cudaGetSymbolAddress((void**)&Wt2, g_Wt2);
    __half* Y1h = (__half*)bufA;              // fp16 Y1
    __half* Fh  = (__half*)bufB;              // fp16 F
    __half* Y2h = (__half*)bufB + (size_t)MROWS * HD / 2;  // fp16 Y2 (2nd half)

    cudaFuncSetAttribute((const void*)gemm_mma_kernel<float>,
                         cudaFuncAttributeMaxDynamicSharedMemorySize, GEMM_SMEM);
    cudaFuncSetAttribute((const void*)gemm_mma_kernel<__half>,
                         cudaFuncAttributeMaxDynamicSharedMemorySize, GEMM_SMEM);

    const dim3 ggrid(HD / BN, MROWS / (2 * BM));   // (8, 128) = 1024 CTAs

    // all input conversions in ONE launch (convA + both weight transposes)
    conv_all_kernel<<<NCA_BLK + NCW_BLK, 256>>>(X, A2, ltw, Wt1, ftw, Wt2);

    // 1) Y1 = X @ lt_w + lt_b   (fp16 out)
    gemm_mma_kernel<__half><<<ggrid, 128, GEMM_SMEM>>>(A2, Wt1, ltb, Y1h);
    // 2) F = fusion(LN1(Y1)) -> fp16, 4 rows/block
    ln1_fusion_kernel<<<MROWS / RPB, 256>>>(Y1h, msk, emb, g1, b1, Fh);
    // 3) agg = multiscale(F), half2-vectorized, SL=64 strips -> A2
    multiscale_kernel<<<(BDIM * H2 * MS_NSTRIP) / 256, 256>>>(
        (const __half2*)Fh, (__half2*)A2);
    // 4) Y2 = agg @ ft_w + ft_b  (fp16 out)
    gemm_mma_kernel<__half><<<ggrid, 128, GEMM_SMEM>>>(A2, Wt2, ftb, Y2h);
    // 5) out = LN2(Y2) + X
    ln2_res_kernel<<<MROWS / RPB, 256>>>(Y2h, X, g2, b2, out);
}